// round 10
// baseline (speedup 1.0000x reference)
#include <cuda_runtime.h>
#include <cuda_fp16.h>
#include <math.h>
#include <stdint.h>

// ---------------- problem sizes ----------------
#define NA 50000
#define NP 100000
#define HC 128
#define NH 8
#define EW 400000
#define ER 400000
#define EC 800000
#define EP (EW + EC)
#define BN_EPS 1e-5f

// ---------------- scratch layout (float units) ----------------
#define OFF_XA    0ull
#define OFF_XP    (OFF_XA   + (size_t)NA*128)
#define OFF_QA    (OFF_XP   + (size_t)NP*128)
#define OFF_QP    (OFF_QA   + (size_t)NA*128)
#define OFF_KVP   (OFF_QP   + (size_t)NP*128)        // half[(NA+NP)*256]
#define OFF_KVA   (OFF_KVP  + (size_t)(NA+NP)*128)   // half[NP*256]
#define OFF_AGGA  (OFF_KVA  + (size_t)NP*128)
#define OFF_AGGP  (OFF_AGGA + (size_t)NA*128)
#define OFF_TMPA  (OFF_AGGP + (size_t)NP*128)
#define OFF_TMPP  (OFF_TMPA + (size_t)NA*128)
#define OFF_WC    (OFF_TMPP + (size_t)NP*128)        // 6 * 128 * 256 composite KV weights
#define OFF_WCB   (OFF_WC   + 6ull*128*256)          // 6 * 256 composite biases
#define OFF_STATS (OFF_WCB  + 6ull*256)
// integer region
#define OFF_INT   (OFF_STATS + 512ull)
#define IOFF_ROWP 0ull
#define IOFF_ROWA (IOFF_ROWP + NP + 1)
#define IOFF_CURP (IOFF_ROWA + NA + 1)
#define IOFF_CURA (IOFF_CURP + NP)
#define IOFF_SRCP (IOFF_CURA + NA)
#define IOFF_SRCA (IOFF_SRCP + EP)
#define IOFF_BS   (IOFF_SRCA + ER)
#define INT_TOTAL (IOFF_BS + 256)
#define TOTAL_FLOATS (OFF_INT + INT_TOTAL + 64ull)

__device__ float g_scratch[TOTAL_FLOATS];

// ---------------- tf32 helpers ----------------
__device__ __forceinline__ uint32_t f2tf32(float x)
{
    uint32_t r;
    asm("cvt.rna.tf32.f32 %0, %1;" : "=r"(r) : "f"(x));
    return r;
}

__device__ __forceinline__ void mma_tf32(float4& c, const uint32_t* a, const uint32_t* b)
{
    asm volatile(
        "mma.sync.aligned.m16n8k8.row.col.f32.tf32.tf32.f32 "
        "{%0,%1,%2,%3}, {%4,%5,%6,%7}, {%8,%9}, {%0,%1,%2,%3};"
        : "+f"(c.x), "+f"(c.y), "+f"(c.z), "+f"(c.w)
        : "r"(a[0]), "r"(a[1]), "r"(a[2]), "r"(a[3]), "r"(b[0]), "r"(b[1]));
}

// ---------------- tf32x2 tensor-core GEMM (R8 mainloop, BN-stats epilogue) -----
// C[M, gridN] = A[M,K] @ W[K,*] + bias. BM=128, BN=128, BK=16, 8 warps 2x4.
// Ch != nullptr -> half output. act: 0=none, 1=relu,
// 2=skip-mix + BN stats accumulation into stats[256] (requires single col tile).
__global__ void __launch_bounds__(256)
gemm_tf32(const float* __restrict__ A, int lda, const float* __restrict__ W, int ldw,
          const float* __restrict__ bias, float* __restrict__ C, __half* __restrict__ Ch,
          int ldc, int M, int K, int act,
          const float* __restrict__ xold, const float* __restrict__ skipv,
          float* __restrict__ stats)
{
    __shared__ uint32_t As[128][20];
    __shared__ uint32_t Bs[16][136], Bl[16][136];
    __shared__ float bnS[256];

    const int bm = blockIdx.y * 128;
    const int bn = blockIdx.x * 128;
    const int tid = threadIdx.x;
    const int lane = tid & 31;
    const int warp = tid >> 5;
    const int wm = warp >> 2;
    const int wn = warp & 3;

    float4 acc[4][4];
#pragma unroll
    for (int i = 0; i < 4; i++)
#pragma unroll
        for (int j = 0; j < 4; j++) acc[i][j] = make_float4(0.f, 0.f, 0.f, 0.f);

    for (int k0 = 0; k0 < K; k0 += 16) {
#pragma unroll
        for (int i = 0; i < 2; i++) {
            int id  = tid + i * 256;
            int row = id >> 2;
            int kc  = (id & 3) * 4;
            int grow = bm + row;
            float4 v = make_float4(0.f, 0.f, 0.f, 0.f);
            if (grow < M) v = *(const float4*)(A + (size_t)grow * lda + k0 + kc);
            As[row][kc + 0] = f2tf32(v.x); As[row][kc + 1] = f2tf32(v.y);
            As[row][kc + 2] = f2tf32(v.z); As[row][kc + 3] = f2tf32(v.w);
        }
#pragma unroll
        for (int i = 0; i < 2; i++) {
            int id  = tid + i * 256;
            int row = id >> 5;
            int col = (id & 31) * 4;
            float4 v = *(const float4*)(W + (size_t)(k0 + row) * ldw + bn + col);
            uint32_t h;
            h = f2tf32(v.x); Bs[row][col + 0] = h; Bl[row][col + 0] = f2tf32(v.x - __uint_as_float(h));
            h = f2tf32(v.y); Bs[row][col + 1] = h; Bl[row][col + 1] = f2tf32(v.y - __uint_as_float(h));
            h = f2tf32(v.z); Bs[row][col + 2] = h; Bl[row][col + 2] = f2tf32(v.z - __uint_as_float(h));
            h = f2tf32(v.w); Bs[row][col + 3] = h; Bl[row][col + 3] = f2tf32(v.w - __uint_as_float(h));
        }
        __syncthreads();

#pragma unroll
        for (int ks = 0; ks < 16; ks += 8) {
            uint32_t af[4][4];
            const int kc = ks + (lane & 3);
#pragma unroll
            for (int mf = 0; mf < 4; mf++) {
                int r = wm * 64 + mf * 16 + (lane >> 2);
                af[mf][0] = As[r][kc];
                af[mf][1] = As[r + 8][kc];
                af[mf][2] = As[r][kc + 4];
                af[mf][3] = As[r + 8][kc + 4];
            }
            uint32_t bh[4][2], bl[4][2];
#pragma unroll
            for (int nf = 0; nf < 4; nf++) {
                int n = wn * 32 + nf * 8 + (lane >> 2);
                bh[nf][0] = Bs[kc][n];     bl[nf][0] = Bl[kc][n];
                bh[nf][1] = Bs[kc + 4][n]; bl[nf][1] = Bl[kc + 4][n];
            }
#pragma unroll
            for (int mf = 0; mf < 4; mf++)
#pragma unroll
                for (int nf = 0; nf < 4; nf++) {
                    mma_tf32(acc[mf][nf], af[mf], bl[nf]);
                    mma_tf32(acc[mf][nf], af[mf], bh[nf]);
                }
        }
        __syncthreads();
    }

    const int lr = lane >> 2;
    const int lc = (lane & 3) * 2;
    float sk = 0.f;
    if (act == 2) sk = 1.f / (1.f + __expf(-skipv[0]));
    float2 bv[4];
#pragma unroll
    for (int nf = 0; nf < 4; nf++) {
        int c0 = bn + wn * 32 + nf * 8 + lc;
        bv[nf] = *(const float2*)(bias + c0);
    }

    float cs[4][2] = {{0.f,0.f},{0.f,0.f},{0.f,0.f},{0.f,0.f}};
    float cq[4][2] = {{0.f,0.f},{0.f,0.f},{0.f,0.f},{0.f,0.f}};

#pragma unroll
    for (int mf = 0; mf < 4; mf++) {
        int r0 = bm + wm * 64 + mf * 16 + lr;
        int r1 = r0 + 8;
#pragma unroll
        for (int nf = 0; nf < 4; nf++) {
            int c0 = bn + wn * 32 + nf * 8 + lc;
            float4 a = acc[mf][nf];
            float2 o0 = make_float2(a.x + bv[nf].x, a.y + bv[nf].y);
            float2 o1 = make_float2(a.z + bv[nf].x, a.w + bv[nf].y);
            if (act == 1) {
                o0.x = fmaxf(o0.x, 0.f); o0.y = fmaxf(o0.y, 0.f);
                o1.x = fmaxf(o1.x, 0.f); o1.y = fmaxf(o1.y, 0.f);
            } else if (act == 2) {
                if (r0 < M) {
                    float2 x0 = *(const float2*)(xold + (size_t)r0 * ldc + c0);
                    o0.x = sk * o0.x + (1.f - sk) * x0.x;
                    o0.y = sk * o0.y + (1.f - sk) * x0.y;
                    cs[nf][0] += o0.x; cs[nf][1] += o0.y;
                    cq[nf][0] += o0.x * o0.x; cq[nf][1] += o0.y * o0.y;
                }
                if (r1 < M) {
                    float2 x1 = *(const float2*)(xold + (size_t)r1 * ldc + c0);
                    o1.x = sk * o1.x + (1.f - sk) * x1.x;
                    o1.y = sk * o1.y + (1.f - sk) * x1.y;
                    cs[nf][0] += o1.x; cs[nf][1] += o1.y;
                    cq[nf][0] += o1.x * o1.x; cq[nf][1] += o1.y * o1.y;
                }
            }
            if (Ch) {
                if (r0 < M) *(__half2*)(Ch + (size_t)r0 * ldc + c0) = __floats2half2_rn(o0.x, o0.y);
                if (r1 < M) *(__half2*)(Ch + (size_t)r1 * ldc + c0) = __floats2half2_rn(o1.x, o1.y);
            } else {
                if (r0 < M) *(float2*)(C + (size_t)r0 * ldc + c0) = o0;
                if (r1 < M) *(float2*)(C + (size_t)r1 * ldc + c0) = o1;
            }
        }
    }

    if (act == 2) {
        bnS[tid] = 0.f;
        __syncthreads();
#pragma unroll
        for (int nf = 0; nf < 4; nf++) {
            int ccol = wn * 32 + nf * 8 + lc;
            atomicAdd(&bnS[ccol],       cs[nf][0]);
            atomicAdd(&bnS[ccol + 1],   cs[nf][1]);
            atomicAdd(&bnS[128 + ccol],     cq[nf][0]);
            atomicAdd(&bnS[128 + ccol + 1], cq[nf][1]);
        }
        __syncthreads();
        atomicAdd(&stats[tid], bnS[tid]);
    }
}

// ---------------- composite KV weights ----------------
__global__ void wcomp(const float* __restrict__ kqv_W, const float* __restrict__ a_k,
                      const float* __restrict__ a_v, float* __restrict__ WC)
{
    int gid = blockIdx.x * blockDim.x + threadIdx.x;
    if (gid >= 6 * 128 * 256) return;
    int lr = gid >> 15;
    int r  = (gid >> 8) & 127;
    int c  = gid & 255;
    int l = lr / 3, rel = lr % 3;
    int t = (rel == 0) ? 0 : 1;
    const float* Wb = kqv_W + (size_t)(l * 2 + t) * 128 * 384 + (size_t)r * 384 + ((c < 128) ? 0 : 256);
    int cc = c & 127;
    int h = cc >> 4, e = cc & 15;
    const float* Am = ((c < 128) ? a_k : a_v) + (size_t)(l * 3 + rel) * 2048 + h * 256 + e;
    float s = 0.f;
#pragma unroll
    for (int dd = 0; dd < 16; dd++) s += Wb[h * 16 + dd] * Am[dd * 16];
    WC[gid] = s;
}

__global__ void bcomp(const float* __restrict__ kqv_b, const float* __restrict__ a_k,
                      const float* __restrict__ a_v, float* __restrict__ WCB)
{
    int gid = blockIdx.x * blockDim.x + threadIdx.x;
    if (gid >= 6 * 256) return;
    int lr = gid >> 8;
    int c  = gid & 255;
    int l = lr / 3, rel = lr % 3;
    int t = (rel == 0) ? 0 : 1;
    const float* bb = kqv_b + (size_t)(l * 2 + t) * 384 + ((c < 128) ? 0 : 256);
    int cc = c & 127;
    int h = cc >> 4, e = cc & 15;
    const float* Am = ((c < 128) ? a_k : a_v) + (size_t)(l * 3 + rel) * 2048 + h * 256 + e;
    float s = 0.f;
#pragma unroll
    for (int dd = 0; dd < 16; dd++) s += bb[h * 16 + dd] * Am[dd * 16];
    WCB[gid] = s;
}

// ---------------- CSR build ----------------
__global__ void hist_kernel(const int* __restrict__ dst, int* __restrict__ deg, int E)
{
    int i = blockIdx.x * blockDim.x + threadIdx.x;
    if (i < E) atomicAdd(&deg[dst[i]], 1);
}

__global__ void scan_partial(const int* __restrict__ deg, int* __restrict__ row,
                             int* __restrict__ bsums, int n)
{
    __shared__ int warpsum[8];
    int t = threadIdx.x;
    int lane = t & 31, wid = t >> 5;
    int base = blockIdx.x * 1024 + t * 4;
    int v0 = (base + 0 < n) ? deg[base + 0] : 0;
    int v1 = (base + 1 < n) ? deg[base + 1] : 0;
    int v2 = (base + 2 < n) ? deg[base + 2] : 0;
    int v3 = (base + 3 < n) ? deg[base + 3] : 0;
    int e0 = 0, e1 = v0, e2 = e1 + v1, e3 = e2 + v2;
    int tot = e3 + v3;
    int inc = tot;
#pragma unroll
    for (int off = 1; off < 32; off <<= 1) {
        int y = __shfl_up_sync(0xffffffffu, inc, off);
        if (lane >= off) inc += y;
    }
    if (lane == 31) warpsum[wid] = inc;
    __syncthreads();
    if (wid == 0) {
        int w = (lane < 8) ? warpsum[lane] : 0;
#pragma unroll
        for (int off = 1; off < 8; off <<= 1) {
            int y = __shfl_up_sync(0xffffffffu, w, off);
            if (lane >= off) w += y;
        }
        if (lane < 8) warpsum[lane] = w;
    }
    __syncthreads();
    int warpExcl = (wid == 0) ? 0 : warpsum[wid - 1];
    int thrExcl = warpExcl + inc - tot;
    if (base + 0 < n) row[base + 0] = thrExcl + e0;
    if (base + 1 < n) row[base + 1] = thrExcl + e1;
    if (base + 2 < n) row[base + 2] = thrExcl + e2;
    if (base + 3 < n) row[base + 3] = thrExcl + e3;
    if (t == 0) bsums[blockIdx.x] = warpsum[7];
}

__global__ void scan_small(int* __restrict__ bsums, int nb)
{
    __shared__ int warpsum[8];
    int t = threadIdx.x;
    int lane = t & 31, wid = t >> 5;
    int v = (t < nb) ? bsums[t] : 0;
    int inc = v;
#pragma unroll
    for (int off = 1; off < 32; off <<= 1) {
        int y = __shfl_up_sync(0xffffffffu, inc, off);
        if (lane >= off) inc += y;
    }
    if (lane == 31) warpsum[wid] = inc;
    __syncthreads();
    if (wid == 0) {
        int w = (lane < 8) ? warpsum[lane] : 0;
#pragma unroll
        for (int off = 1; off < 8; off <<= 1) {
            int y = __shfl_up_sync(0xffffffffu, w, off);
            if (lane >= off) w += y;
        }
        if (lane < 8) warpsum[lane] = w;
    }
    __syncthreads();
    int warpExcl = (wid == 0) ? 0 : warpsum[wid - 1];
    int excl = warpExcl + inc - v;
    if (t < nb) bsums[t] = excl;
    if (t == 255) bsums[nb] = warpExcl + inc;
}

__global__ void add_off(int* __restrict__ row, int* __restrict__ cur,
                        const int* __restrict__ bsums, int n, int nb)
{
    int i = blockIdx.x * blockDim.x + threadIdx.x;
    if (i < n) {
        int r = row[i] + bsums[i >> 10];
        row[i] = r;
        cur[i] = r;
    }
    if (i == 0) row[n] = bsums[nb];
}

__global__ void scatter_kernel(const int* __restrict__ src, const int* __restrict__ dst,
                               int* __restrict__ cursor, int* __restrict__ out,
                               int E, int srcOffset)
{
    int i = blockIdx.x * blockDim.x + threadIdx.x;
    if (i >= E) return;
    int p = atomicAdd(&cursor[dst[i]], 1);
    out[p] = src[i] + srcOffset;
}

// ---------------- fused attention (both node types in one launch) ----------------
// warps [0, NP): paper destinations; warps [NP, NP+NA): author destinations.
__global__ void attn_agg2(const float* __restrict__ QP, const __half* __restrict__ KVP,
                          const int* __restrict__ rowP, const int* __restrict__ srcP,
                          const float* __restrict__ prelP_A, const float* __restrict__ prelP_B,
                          const float* __restrict__ QA, const __half* __restrict__ KVA,
                          const int* __restrict__ rowA, const int* __restrict__ srcA,
                          const float* __restrict__ prelA_r,
                          float* __restrict__ aggP, float* __restrict__ aggA)
{
    int gwarp = (blockIdx.x * blockDim.x + threadIdx.x) >> 5;
    int lane = threadIdx.x & 31;
    if (gwarp >= NP + NA) return;

    const float* Q; const __half* KV; const int* rowptr; const int* srccol;
    const float* prA; const float* prB; int relB; float* agg; int node;
    if (gwarp < NP) {
        node = gwarp; Q = QP; KV = KVP; rowptr = rowP; srccol = srcP;
        prA = prelP_A; prB = prelP_B; relB = NA; agg = aggP;
    } else {
        node = gwarp - NP; Q = QA; KV = KVA; rowptr = rowA; srccol = srcA;
        prA = prelA_r; prB = prelA_r; relB = NP + 1; agg = aggA;
    }

    int h = lane >> 2;
    int c = h * 16 + (lane & 3) * 4;
    float4 q4 = *(const float4*)(Q + (size_t)node * 128 + c);
    float pA = prA[h] * 0.25f;
    float pB = prB[h] * 0.25f;
    int js = rowptr[node], je = rowptr[node + 1];
    float m = -INFINITY, s = 0.f;
    float4 acc = make_float4(0.f, 0.f, 0.f, 0.f);

    int j = js;
    for (; j + 1 < je; j += 2) {
        int sr1 = srccol[j];
        int sr2 = srccol[j + 1];
        const __half2* kp1 = (const __half2*)(KV + (size_t)sr1 * 256 + c);
        const __half2* kp2 = (const __half2*)(KV + (size_t)sr2 * 256 + c);
        float2 k10 = __half22float2(kp1[0]), k11 = __half22float2(kp1[1]);
        float2 k20 = __half22float2(kp2[0]), k21 = __half22float2(kp2[1]);
        float p1 = q4.x * k10.x + q4.y * k10.y + q4.z * k11.x + q4.w * k11.y;
        float p2 = q4.x * k20.x + q4.y * k20.y + q4.z * k21.x + q4.w * k21.y;
        p1 += __shfl_xor_sync(0xffffffffu, p1, 1);
        p2 += __shfl_xor_sync(0xffffffffu, p2, 1);
        p1 += __shfl_xor_sync(0xffffffffu, p1, 2);
        p2 += __shfl_xor_sync(0xffffffffu, p2, 2);
        float a1 = p1 * ((sr1 >= relB) ? pB : pA);
        float a2 = p2 * ((sr2 >= relB) ? pB : pA);
        const __half2* vp1 = (const __half2*)(KV + (size_t)sr1 * 256 + 128 + c);
        const __half2* vp2 = (const __half2*)(KV + (size_t)sr2 * 256 + 128 + c);
        float2 v10 = __half22float2(vp1[0]), v11 = __half22float2(vp1[1]);
        float2 v20 = __half22float2(vp2[0]), v21 = __half22float2(vp2[1]);
        float newm = fmaxf(m, fmaxf(a1, a2));
        float scl = __expf(m - newm);
        float w1 = __expf(a1 - newm);
        float w2 = __expf(a2 - newm);
        s = s * scl + w1 + w2;
        acc.x = acc.x * scl + w1 * v10.x + w2 * v20.x;
        acc.y = acc.y * scl + w1 * v10.y + w2 * v20.y;
        acc.z = acc.z * scl + w1 * v11.x + w2 * v21.x;
        acc.w = acc.w * scl + w1 * v11.y + w2 * v21.y;
        m = newm;
    }
    for (; j < je; j++) {
        int sr = srccol[j];
        const __half2* kp = (const __half2*)(KV + (size_t)sr * 256 + c);
        float2 k0 = __half22float2(kp[0]), k1 = __half22float2(kp[1]);
        float part = q4.x * k0.x + q4.y * k0.y + q4.z * k1.x + q4.w * k1.y;
        part += __shfl_xor_sync(0xffffffffu, part, 1);
        part += __shfl_xor_sync(0xffffffffu, part, 2);
        float a = part * ((sr >= relB) ? pB : pA);
        float newm = fmaxf(m, a);
        float scl = __expf(m - newm);
        float w = __expf(a - newm);
        s = s * scl + w;
        const __half2* vp = (const __half2*)(KV + (size_t)sr * 256 + 128 + c);
        float2 v0 = __half22float2(vp[0]), v1 = __half22float2(vp[1]);
        acc.x = acc.x * scl + w * v0.x;
        acc.y = acc.y * scl + w * v0.y;
        acc.z = acc.z * scl + w * v1.x;
        acc.w = acc.w * scl + w * v1.y;
        m = newm;
    }

    float inv = 1.f / (s + 1e-16f);
    float4 r;
    float v;
    v = acc.x * inv; r.x = 0.5f * v * (1.f + erff(v * 0.70710678118654752f));
    v = acc.y * inv; r.y = 0.5f * v * (1.f + erff(v * 0.70710678118654752f));
    v = acc.z * inv; r.z = 0.5f * v * (1.f + erff(v * 0.70710678118654752f));
    v = acc.w * inv; r.w = 0.5f * v * (1.f + erff(v * 0.70710678118654752f));
    *(float4*)(agg + (size_t)node * 128 + c) = r;
}

// ---------------- BatchNorm apply (both node types in one launch) ----------------
__global__ void bn_apply2(const float* __restrict__ hA, const float* __restrict__ hP,
                          const float* __restrict__ stats,  // [0:256) author, [256:512) paper
                          const float* __restrict__ gamma, const float* __restrict__ beta,
                          float* __restrict__ outA, float* __restrict__ outP)
{
    int i = blockIdx.x * blockDim.x + threadIdx.x;
    const int totA = NA * 128;
    const int totP = NP * 128;
    if (i < totA) {
        int c = i & 127;
        float invN = 1.f / (float)NA;
        float mu = stats[c] * invN;
        float var = stats[128 + c] * invN - mu * mu;
        outA[i] = (hA[i] - mu) * rsqrtf(var + BN_EPS) * gamma[c] + beta[c];
    } else {
        int k = i - totA;
        if (k >= totP) return;
        int c = k & 127;
        float invN = 1.f / (float)NP;
        float mu = stats[256 + c] * invN;
        float var = stats[256 + 128 + c] * invN - mu * mu;
        outP[k] = (hP[k] - mu) * rsqrtf(var + BN_EPS) * gamma[c] + beta[c];
    }
}

// ---------------------------------------------------------------
static inline int cdiv(long long a, long long b) { return (int)((a + b - 1) / b); }

extern "C" void kernel_launch(void* const* d_in, const int* in_sizes, int n_in,
                              void* d_out, int out_size)
{
    const float* x_author = (const float*)d_in[0];
    const float* x_paper  = (const float*)d_in[1];
    const int* writes_src = (const int*)d_in[2];
    const int* writes_dst = (const int*)d_in[3];
    const int* rev_src    = (const int*)d_in[4];
    const int* rev_dst    = (const int*)d_in[5];
    const int* cites_src  = (const int*)d_in[6];
    const int* cites_dst  = (const int*)d_in[7];
    const float* linA_W   = (const float*)d_in[8];
    const float* linA_b   = (const float*)d_in[9];
    const float* linP_W   = (const float*)d_in[10];
    const float* linP_b   = (const float*)d_in[11];
    const float* kqv_W    = (const float*)d_in[12];
    const float* kqv_b    = (const float*)d_in[13];
    const float* a_k      = (const float*)d_in[14];
    const float* a_v      = (const float*)d_in[15];
    const float* p_rel    = (const float*)d_in[16];
    const float* out_W    = (const float*)d_in[17];
    const float* out_b    = (const float*)d_in[18];
    const float* skipP    = (const float*)d_in[19];
    const float* bn_gamma = (const float*)d_in[20];
    const float* bn_beta  = (const float*)d_in[21];

    float* base = nullptr;
    cudaGetSymbolAddress((void**)&base, g_scratch);

    float* XA   = base + OFF_XA;
    float* XP   = base + OFF_XP;
    float* QA   = base + OFF_QA;
    float* QP   = base + OFF_QP;
    __half* KVP = (__half*)(base + OFF_KVP);
    __half* KVA = (__half*)(base + OFF_KVA);
    float* AGGA = base + OFF_AGGA;
    float* AGGP = base + OFF_AGGP;
    float* TMPA = base + OFF_TMPA;
    float* TMPP = base + OFF_TMPP;
    float* WC   = base + OFF_WC;
    float* WCB  = base + OFF_WCB;
    float* STA  = base + OFF_STATS;
    float* STP  = base + OFF_STATS + 256;
    int* ibase  = (int*)(base + OFF_INT);
    int* ROWP   = ibase + IOFF_ROWP;
    int* ROWA   = ibase + IOFF_ROWA;
    int* CURP   = ibase + IOFF_CURP;
    int* CURA   = ibase + IOFF_CURA;
    int* SRCP   = ibase + IOFF_SRCP;
    int* SRCA   = ibase + IOFF_SRCA;
    int* BS     = ibase + IOFF_BS;

    // -------- CSR build + composite weights (x-independent) --------
    const int nbP = cdiv(NP, 1024), nbA = cdiv(NA, 1024);
    cudaMemsetAsync(CURP, 0, (size_t)NP * 4, 0);
    cudaMemsetAsync(CURA, 0, (size_t)NA * 4, 0);
    hist_kernel<<<cdiv(EW, 256), 256>>>(writes_dst, CURP, EW);
    hist_kernel<<<cdiv(EC, 256), 256>>>(cites_dst, CURP, EC);
    hist_kernel<<<cdiv(ER, 256), 256>>>(rev_dst, CURA, ER);
    scan_partial<<<nbP, 256>>>(CURP, ROWP, BS, NP);
    scan_small<<<1, 256>>>(BS, nbP);
    add_off<<<cdiv(NP, 256), 256>>>(ROWP, CURP, BS, NP, nbP);
    scan_partial<<<nbA, 256>>>(CURA, ROWA, BS, NA);
    scan_small<<<1, 256>>>(BS, nbA);
    add_off<<<cdiv(NA, 256), 256>>>(ROWA, CURA, BS, NA, nbA);
    scatter_kernel<<<cdiv(EW, 256), 256>>>(writes_src, writes_dst, CURP, SRCP, EW, 0);
    scatter_kernel<<<cdiv(EC, 256), 256>>>(cites_src, cites_dst, CURP, SRCP, EC, NA);
    scatter_kernel<<<cdiv(ER, 256), 256>>>(rev_src, rev_dst, CURA, SRCA, ER, 0);
    wcomp<<<768, 256>>>(kqv_W, a_k, a_v, WC);
    bcomp<<<6, 256>>>(kqv_b, a_k, a_v, WCB);

    // -------- input projections + relu --------
    gemm_tf32<<<dim3(1, cdiv(NA, 128)), 256>>>(x_author, 128, linA_W, 128, linA_b,
                                               XA, nullptr, 128, NA, 128, 1, nullptr, nullptr, nullptr);
    gemm_tf32<<<dim3(1, cdiv(NP, 128)), 256>>>(x_paper, 128, linP_W, 128, linP_b,
                                               XP, nullptr, 128, NP, 128, 1, nullptr, nullptr, nullptr);

    for (int l = 0; l < 2; l++) {
        // Q projections (Q slice of kqv weights: cols [128,256))
        gemm_tf32<<<dim3(1, cdiv(NA, 128)), 256>>>(XA, 128, kqv_W + (size_t)(l * 2 + 0) * 128 * 384 + 128, 384,
                                                   kqv_b + (size_t)(l * 2 + 0) * 384 + 128,
                                                   QA, nullptr, 128, NA, 128, 0, nullptr, nullptr, nullptr);
        gemm_tf32<<<dim3(1, cdiv(NP, 128)), 256>>>(XP, 128, kqv_W + (size_t)(l * 2 + 1) * 128 * 384 + 128, 384,
                                                   kqv_b + (size_t)(l * 2 + 1) * 384 + 128,
                                                   QP, nullptr, 128, NP, 128, 0, nullptr, nullptr, nullptr);

        // combined K|V tables via composite weights, fp16 output
        gemm_tf32<<<dim3(2, cdiv(NA, 128)), 256>>>(XA, 128, WC + (size_t)(l * 3 + 0) * 128 * 256, 256,
                                                   WCB + (size_t)(l * 3 + 0) * 256,
                                                   nullptr, KVP, 256, NA, 128, 0, nullptr, nullptr, nullptr);
        gemm_tf32<<<dim3(2, cdiv(NP, 128)), 256>>>(XP, 128, WC + (size_t)(l * 3 + 2) * 128 * 256, 256,
                                                   WCB + (size_t)(l * 3 + 2) * 256,
                                                   nullptr, KVP + (size_t)NA * 256, 256, NP, 128, 0, nullptr, nullptr, nullptr);
        gemm_tf32<<<dim3(2, cdiv(NP, 128)), 256>>>(XP, 128, WC + (size_t)(l * 3 + 1) * 128 * 256, 256,
                                                   WCB + (size_t)(l * 3 + 1) * 256,
                                                   nullptr, KVA, 256, NP, 128, 0, nullptr, nullptr, nullptr);

        // fused attention + softmax + aggregation + gelu (single launch, both types)
        attn_agg2<<<cdiv((long long)(NP + NA) * 32, 256), 256>>>(
            QP, KVP, ROWP, SRCP,
            p_rel + (size_t)(l * 3 + 0) * NH, p_rel + (size_t)(l * 3 + 2) * NH,
            QA, KVA, ROWA, SRCA,
            p_rel + (size_t)(l * 3 + 1) * NH,
            AGGP, AGGA);

        // output projection + fused skip-mix + fused BN stats
        cudaMemsetAsync(STA, 0, 512 * 4, 0);
        gemm_tf32<<<dim3(1, cdiv(NA, 128)), 256>>>(AGGA, 128, out_W + (size_t)(l * 2 + 0) * 128 * 128, 128,
                                                   out_b + (size_t)(l * 2 + 0) * 128,
                                                   TMPA, nullptr, 128, NA, 128, 2, XA, skipP + (l * 2 + 0), STA);
        gemm_tf32<<<dim3(1, cdiv(NP, 128)), 256>>>(AGGP, 128, out_W + (size_t)(l * 2 + 1) * 128 * 128, 128,
                                                   out_b + (size_t)(l * 2 + 1) * 128,
                                                   TMPP, nullptr, 128, NP, 128, 2, XP, skipP + (l * 2 + 1), STP);

        // batch norm apply (single launch, both types)
        float* outA = (l == 1) ? (float*)d_out : XA;
        float* outP = (l == 1) ? (float*)d_out + (size_t)NA * 128 : XP;
        bn_apply2<<<cdiv((long long)(NA + NP) * 128, 256), 256>>>(TMPA, TMPP, STA,
                                                                  bn_gamma + (size_t)l * 128,
                                                                  bn_beta + (size_t)l * 128,
                                                                  outA, outP);
    }
}

// round 11
// speedup vs baseline: 1.3531x; 1.3531x over previous
#include <cuda_runtime.h>
#include <cuda_fp16.h>
#include <math.h>
#include <stdint.h>

// ---------------- problem sizes ----------------
#define NA 50000
#define NP 100000
#define HC 128
#define NH 8
#define EW 400000
#define ER 400000
#define EC 800000
#define EP (EW + EC)
#define BN_EPS 1e-5f

// ---------------- scratch layout (float units) ----------------
#define OFF_XA    0ull
#define OFF_XP    (OFF_XA   + (size_t)NA*128)
#define OFF_QA    (OFF_XP   + (size_t)NP*128)
#define OFF_QP    (OFF_QA   + (size_t)NA*128)
#define OFF_KVP   (OFF_QP   + (size_t)NP*128)        // half[(NA+NP)*256]
#define OFF_KVA   (OFF_KVP  + (size_t)(NA+NP)*128)   // half[NP*256]
#define OFF_AGGA  (OFF_KVA  + (size_t)NP*128)
#define OFF_AGGP  (OFF_AGGA + (size_t)NA*128)
#define OFF_TMPA  (OFF_AGGP + (size_t)NP*128)
#define OFF_TMPP  (OFF_TMPA + (size_t)NA*128)
#define OFF_WC    (OFF_TMPP + (size_t)NP*128)        // 6 * 128 * 256 composite KV weights
#define OFF_WCB   (OFF_WC   + 6ull*128*256)          // 6 * 256 composite biases
#define OFF_STATS (OFF_WCB  + 6ull*256)
// integer region
#define OFF_INT   (OFF_STATS + 512ull)
#define IOFF_ROWP 0ull
#define IOFF_ROWA (IOFF_ROWP + NP + 1)
#define IOFF_CURP (IOFF_ROWA + NA + 1)
#define IOFF_CURA (IOFF_CURP + NP)
#define IOFF_SRCP (IOFF_CURA + NA)
#define IOFF_SRCA (IOFF_SRCP + EP)
#define IOFF_BS   (IOFF_SRCA + ER)
#define INT_TOTAL (IOFF_BS + 256)
#define TOTAL_FLOATS (OFF_INT + INT_TOTAL + 64ull)

__device__ float g_scratch[TOTAL_FLOATS];

// ---------------- tf32 helpers ----------------
__device__ __forceinline__ uint32_t f2tf32(float x)
{
    uint32_t r;
    asm("cvt.rna.tf32.f32 %0, %1;" : "=r"(r) : "f"(x));
    return r;
}

__device__ __forceinline__ void mma_tf32(float4& c, const uint32_t* a, const uint32_t* b)
{
    asm volatile(
        "mma.sync.aligned.m16n8k8.row.col.f32.tf32.tf32.f32 "
        "{%0,%1,%2,%3}, {%4,%5,%6,%7}, {%8,%9}, {%0,%1,%2,%3};"
        : "+f"(c.x), "+f"(c.y), "+f"(c.z), "+f"(c.w)
        : "r"(a[0]), "r"(a[1]), "r"(a[2]), "r"(a[3]), "r"(b[0]), "r"(b[1]));
}

// ---------------- tf32x2 tensor-core GEMM (EXACT R8 form) ----------------
// C[M, gridN] = A[M,K] @ W[K,*] + bias. BM=128, BN=128, BK=16, 8 warps 2x4.
// Ch != nullptr -> half output (C ignored). act: 0=none, 1=relu, 2=skip-mix
__global__ void __launch_bounds__(256)
gemm_tf32(const float* __restrict__ A, int lda, const float* __restrict__ W, int ldw,
          const float* __restrict__ bias, float* __restrict__ C, __half* __restrict__ Ch,
          int ldc, int M, int K, int act,
          const float* __restrict__ xold, const float* __restrict__ skipv)
{
    __shared__ uint32_t As[128][20];
    __shared__ uint32_t Bs[16][136], Bl[16][136];

    const int bm = blockIdx.y * 128;
    const int bn = blockIdx.x * 128;
    const int tid = threadIdx.x;
    const int lane = tid & 31;
    const int warp = tid >> 5;
    const int wm = warp >> 2;
    const int wn = warp & 3;

    float4 acc[4][4];
#pragma unroll
    for (int i = 0; i < 4; i++)
#pragma unroll
        for (int j = 0; j < 4; j++) acc[i][j] = make_float4(0.f, 0.f, 0.f, 0.f);

    for (int k0 = 0; k0 < K; k0 += 16) {
#pragma unroll
        for (int i = 0; i < 2; i++) {
            int id  = tid + i * 256;
            int row = id >> 2;
            int kc  = (id & 3) * 4;
            int grow = bm + row;
            float4 v = make_float4(0.f, 0.f, 0.f, 0.f);
            if (grow < M) v = *(const float4*)(A + (size_t)grow * lda + k0 + kc);
            As[row][kc + 0] = f2tf32(v.x); As[row][kc + 1] = f2tf32(v.y);
            As[row][kc + 2] = f2tf32(v.z); As[row][kc + 3] = f2tf32(v.w);
        }
#pragma unroll
        for (int i = 0; i < 2; i++) {
            int id  = tid + i * 256;
            int row = id >> 5;
            int col = (id & 31) * 4;
            float4 v = *(const float4*)(W + (size_t)(k0 + row) * ldw + bn + col);
            uint32_t h;
            h = f2tf32(v.x); Bs[row][col + 0] = h; Bl[row][col + 0] = f2tf32(v.x - __uint_as_float(h));
            h = f2tf32(v.y); Bs[row][col + 1] = h; Bl[row][col + 1] = f2tf32(v.y - __uint_as_float(h));
            h = f2tf32(v.z); Bs[row][col + 2] = h; Bl[row][col + 2] = f2tf32(v.z - __uint_as_float(h));
            h = f2tf32(v.w); Bs[row][col + 3] = h; Bl[row][col + 3] = f2tf32(v.w - __uint_as_float(h));
        }
        __syncthreads();

#pragma unroll
        for (int ks = 0; ks < 16; ks += 8) {
            uint32_t af[4][4];
            const int kc = ks + (lane & 3);
#pragma unroll
            for (int mf = 0; mf < 4; mf++) {
                int r = wm * 64 + mf * 16 + (lane >> 2);
                af[mf][0] = As[r][kc];
                af[mf][1] = As[r + 8][kc];
                af[mf][2] = As[r][kc + 4];
                af[mf][3] = As[r + 8][kc + 4];
            }
            uint32_t bh[4][2], bl[4][2];
#pragma unroll
            for (int nf = 0; nf < 4; nf++) {
                int n = wn * 32 + nf * 8 + (lane >> 2);
                bh[nf][0] = Bs[kc][n];     bl[nf][0] = Bl[kc][n];
                bh[nf][1] = Bs[kc + 4][n]; bl[nf][1] = Bl[kc + 4][n];
            }
#pragma unroll
            for (int mf = 0; mf < 4; mf++)
#pragma unroll
                for (int nf = 0; nf < 4; nf++) {
                    mma_tf32(acc[mf][nf], af[mf], bl[nf]);
                    mma_tf32(acc[mf][nf], af[mf], bh[nf]);
                }
        }
        __syncthreads();
    }

    const int lr = lane >> 2;
    const int lc = (lane & 3) * 2;
    float sk = 0.f;
    if (act == 2) sk = 1.f / (1.f + __expf(-skipv[0]));
    float2 bv[4];
#pragma unroll
    for (int nf = 0; nf < 4; nf++) {
        int c0 = bn + wn * 32 + nf * 8 + lc;
        bv[nf] = *(const float2*)(bias + c0);
    }
#pragma unroll
    for (int mf = 0; mf < 4; mf++) {
        int r0 = bm + wm * 64 + mf * 16 + lr;
        int r1 = r0 + 8;
#pragma unroll
        for (int nf = 0; nf < 4; nf++) {
            int c0 = bn + wn * 32 + nf * 8 + lc;
            float4 a = acc[mf][nf];
            float2 o0 = make_float2(a.x + bv[nf].x, a.y + bv[nf].y);
            float2 o1 = make_float2(a.z + bv[nf].x, a.w + bv[nf].y);
            if (act == 1) {
                o0.x = fmaxf(o0.x, 0.f); o0.y = fmaxf(o0.y, 0.f);
                o1.x = fmaxf(o1.x, 0.f); o1.y = fmaxf(o1.y, 0.f);
            } else if (act == 2) {
                if (r0 < M) {
                    float2 x0 = *(const float2*)(xold + (size_t)r0 * ldc + c0);
                    o0.x = sk * o0.x + (1.f - sk) * x0.x;
                    o0.y = sk * o0.y + (1.f - sk) * x0.y;
                }
                if (r1 < M) {
                    float2 x1 = *(const float2*)(xold + (size_t)r1 * ldc + c0);
                    o1.x = sk * o1.x + (1.f - sk) * x1.x;
                    o1.y = sk * o1.y + (1.f - sk) * x1.y;
                }
            }
            if (Ch) {
                if (r0 < M) *(__half2*)(Ch + (size_t)r0 * ldc + c0) = __floats2half2_rn(o0.x, o0.y);
                if (r1 < M) *(__half2*)(Ch + (size_t)r1 * ldc + c0) = __floats2half2_rn(o1.x, o1.y);
            } else {
                if (r0 < M) *(float2*)(C + (size_t)r0 * ldc + c0) = o0;
                if (r1 < M) *(float2*)(C + (size_t)r1 * ldc + c0) = o1;
            }
        }
    }
}

// ---------------- composite KV weights ----------------
__global__ void wcomp(const float* __restrict__ kqv_W, const float* __restrict__ a_k,
                      const float* __restrict__ a_v, float* __restrict__ WC)
{
    int gid = blockIdx.x * blockDim.x + threadIdx.x;
    if (gid >= 6 * 128 * 256) return;
    int lr = gid >> 15;
    int r  = (gid >> 8) & 127;
    int c  = gid & 255;
    int l = lr / 3, rel = lr % 3;
    int t = (rel == 0) ? 0 : 1;
    const float* Wb = kqv_W + (size_t)(l * 2 + t) * 128 * 384 + (size_t)r * 384 + ((c < 128) ? 0 : 256);
    int cc = c & 127;
    int h = cc >> 4, e = cc & 15;
    const float* Am = ((c < 128) ? a_k : a_v) + (size_t)(l * 3 + rel) * 2048 + h * 256 + e;
    float s = 0.f;
#pragma unroll
    for (int dd = 0; dd < 16; dd++) s += Wb[h * 16 + dd] * Am[dd * 16];
    WC[gid] = s;
}

__global__ void bcomp(const float* __restrict__ kqv_b, const float* __restrict__ a_k,
                      const float* __restrict__ a_v, float* __restrict__ WCB)
{
    int gid = blockIdx.x * blockDim.x + threadIdx.x;
    if (gid >= 6 * 256) return;
    int lr = gid >> 8;
    int c  = gid & 255;
    int l = lr / 3, rel = lr % 3;
    int t = (rel == 0) ? 0 : 1;
    const float* bb = kqv_b + (size_t)(l * 2 + t) * 384 + ((c < 128) ? 0 : 256);
    int cc = c & 127;
    int h = cc >> 4, e = cc & 15;
    const float* Am = ((c < 128) ? a_k : a_v) + (size_t)(l * 3 + rel) * 2048 + h * 256 + e;
    float s = 0.f;
#pragma unroll
    for (int dd = 0; dd < 16; dd++) s += bb[h * 16 + dd] * Am[dd * 16];
    WCB[gid] = s;
}

// ---------------- CSR build ----------------
__global__ void hist_kernel(const int* __restrict__ dst, int* __restrict__ deg, int E)
{
    int i = blockIdx.x * blockDim.x + threadIdx.x;
    if (i < E) atomicAdd(&deg[dst[i]], 1);
}

__global__ void scan_partial(const int* __restrict__ deg, int* __restrict__ row,
                             int* __restrict__ bsums, int n)
{
    __shared__ int warpsum[8];
    int t = threadIdx.x;
    int lane = t & 31, wid = t >> 5;
    int base = blockIdx.x * 1024 + t * 4;
    int v0 = (base + 0 < n) ? deg[base + 0] : 0;
    int v1 = (base + 1 < n) ? deg[base + 1] : 0;
    int v2 = (base + 2 < n) ? deg[base + 2] : 0;
    int v3 = (base + 3 < n) ? deg[base + 3] : 0;
    int e0 = 0, e1 = v0, e2 = e1 + v1, e3 = e2 + v2;
    int tot = e3 + v3;
    int inc = tot;
#pragma unroll
    for (int off = 1; off < 32; off <<= 1) {
        int y = __shfl_up_sync(0xffffffffu, inc, off);
        if (lane >= off) inc += y;
    }
    if (lane == 31) warpsum[wid] = inc;
    __syncthreads();
    if (wid == 0) {
        int w = (lane < 8) ? warpsum[lane] : 0;
#pragma unroll
        for (int off = 1; off < 8; off <<= 1) {
            int y = __shfl_up_sync(0xffffffffu, w, off);
            if (lane >= off) w += y;
        }
        if (lane < 8) warpsum[lane] = w;
    }
    __syncthreads();
    int warpExcl = (wid == 0) ? 0 : warpsum[wid - 1];
    int thrExcl = warpExcl + inc - tot;
    if (base + 0 < n) row[base + 0] = thrExcl + e0;
    if (base + 1 < n) row[base + 1] = thrExcl + e1;
    if (base + 2 < n) row[base + 2] = thrExcl + e2;
    if (base + 3 < n) row[base + 3] = thrExcl + e3;
    if (t == 0) bsums[blockIdx.x] = warpsum[7];
}

__global__ void scan_small(int* __restrict__ bsums, int nb)
{
    __shared__ int warpsum[8];
    int t = threadIdx.x;
    int lane = t & 31, wid = t >> 5;
    int v = (t < nb) ? bsums[t] : 0;
    int inc = v;
#pragma unroll
    for (int off = 1; off < 32; off <<= 1) {
        int y = __shfl_up_sync(0xffffffffu, inc, off);
        if (lane >= off) inc += y;
    }
    if (lane == 31) warpsum[wid] = inc;
    __syncthreads();
    if (wid == 0) {
        int w = (lane < 8) ? warpsum[lane] : 0;
#pragma unroll
        for (int off = 1; off < 8; off <<= 1) {
            int y = __shfl_up_sync(0xffffffffu, w, off);
            if (lane >= off) w += y;
        }
        if (lane < 8) warpsum[lane] = w;
    }
    __syncthreads();
    int warpExcl = (wid == 0) ? 0 : warpsum[wid - 1];
    int excl = warpExcl + inc - v;
    if (t < nb) bsums[t] = excl;
    if (t == 255) bsums[nb] = warpExcl + inc;
}

__global__ void add_off(int* __restrict__ row, int* __restrict__ cur,
                        const int* __restrict__ bsums, int n, int nb)
{
    int i = blockIdx.x * blockDim.x + threadIdx.x;
    if (i < n) {
        int r = row[i] + bsums[i >> 10];
        row[i] = r;
        cur[i] = r;
    }
    if (i == 0) row[n] = bsums[nb];
}

__global__ void scatter_kernel(const int* __restrict__ src, const int* __restrict__ dst,
                               int* __restrict__ cursor, int* __restrict__ out,
                               int E, int srcOffset)
{
    int i = blockIdx.x * blockDim.x + threadIdx.x;
    if (i >= E) return;
    int p = atomicAdd(&cursor[dst[i]], 1);
    out[p] = src[i] + srcOffset;
}

// ---------------- fused attention (both node types in one launch) ----------------
// warps [0, NP): paper destinations; warps [NP, NP+NA): author destinations.
__global__ void attn_agg2(const float* __restrict__ QP, const __half* __restrict__ KVP,
                          const int* __restrict__ rowP, const int* __restrict__ srcP,
                          const float* __restrict__ prelP_A, const float* __restrict__ prelP_B,
                          const float* __restrict__ QA, const __half* __restrict__ KVA,
                          const int* __restrict__ rowA, const int* __restrict__ srcA,
                          const float* __restrict__ prelA_r,
                          float* __restrict__ aggP, float* __restrict__ aggA)
{
    int gwarp = (blockIdx.x * blockDim.x + threadIdx.x) >> 5;
    int lane = threadIdx.x & 31;
    if (gwarp >= NP + NA) return;

    const float* Q; const __half* KV; const int* rowptr; const int* srccol;
    const float* prA; const float* prB; int relB; float* agg; int node;
    if (gwarp < NP) {
        node = gwarp; Q = QP; KV = KVP; rowptr = rowP; srccol = srcP;
        prA = prelP_A; prB = prelP_B; relB = NA; agg = aggP;
    } else {
        node = gwarp - NP; Q = QA; KV = KVA; rowptr = rowA; srccol = srcA;
        prA = prelA_r; prB = prelA_r; relB = NP + 1; agg = aggA;
    }

    int h = lane >> 2;
    int c = h * 16 + (lane & 3) * 4;
    float4 q4 = *(const float4*)(Q + (size_t)node * 128 + c);
    float pA = prA[h] * 0.25f;
    float pB = prB[h] * 0.25f;
    int js = rowptr[node], je = rowptr[node + 1];
    float m = -INFINITY, s = 0.f;
    float4 acc = make_float4(0.f, 0.f, 0.f, 0.f);

    int j = js;
    for (; j + 1 < je; j += 2) {
        int sr1 = srccol[j];
        int sr2 = srccol[j + 1];
        const __half2* kp1 = (const __half2*)(KV + (size_t)sr1 * 256 + c);
        const __half2* kp2 = (const __half2*)(KV + (size_t)sr2 * 256 + c);
        float2 k10 = __half22float2(kp1[0]), k11 = __half22float2(kp1[1]);
        float2 k20 = __half22float2(kp2[0]), k21 = __half22float2(kp2[1]);
        float p1 = q4.x * k10.x + q4.y * k10.y + q4.z * k11.x + q4.w * k11.y;
        float p2 = q4.x * k20.x + q4.y * k20.y + q4.z * k21.x + q4.w * k21.y;
        p1 += __shfl_xor_sync(0xffffffffu, p1, 1);
        p2 += __shfl_xor_sync(0xffffffffu, p2, 1);
        p1 += __shfl_xor_sync(0xffffffffu, p1, 2);
        p2 += __shfl_xor_sync(0xffffffffu, p2, 2);
        float a1 = p1 * ((sr1 >= relB) ? pB : pA);
        float a2 = p2 * ((sr2 >= relB) ? pB : pA);
        const __half2* vp1 = (const __half2*)(KV + (size_t)sr1 * 256 + 128 + c);
        const __half2* vp2 = (const __half2*)(KV + (size_t)sr2 * 256 + 128 + c);
        float2 v10 = __half22float2(vp1[0]), v11 = __half22float2(vp1[1]);
        float2 v20 = __half22float2(vp2[0]), v21 = __half22float2(vp2[1]);
        float newm = fmaxf(m, fmaxf(a1, a2));
        float scl = __expf(m - newm);
        float w1 = __expf(a1 - newm);
        float w2 = __expf(a2 - newm);
        s = s * scl + w1 + w2;
        acc.x = acc.x * scl + w1 * v10.x + w2 * v20.x;
        acc.y = acc.y * scl + w1 * v10.y + w2 * v20.y;
        acc.z = acc.z * scl + w1 * v11.x + w2 * v21.x;
        acc.w = acc.w * scl + w1 * v11.y + w2 * v21.y;
        m = newm;
    }
    for (; j < je; j++) {
        int sr = srccol[j];
        const __half2* kp = (const __half2*)(KV + (size_t)sr * 256 + c);
        float2 k0 = __half22float2(kp[0]), k1 = __half22float2(kp[1]);
        float part = q4.x * k0.x + q4.y * k0.y + q4.z * k1.x + q4.w * k1.y;
        part += __shfl_xor_sync(0xffffffffu, part, 1);
        part += __shfl_xor_sync(0xffffffffu, part, 2);
        float a = part * ((sr >= relB) ? pB : pA);
        float newm = fmaxf(m, a);
        float scl = __expf(m - newm);
        float w = __expf(a - newm);
        s = s * scl + w;
        const __half2* vp = (const __half2*)(KV + (size_t)sr * 256 + 128 + c);
        float2 v0 = __half22float2(vp[0]), v1 = __half22float2(vp[1]);
        acc.x = acc.x * scl + w * v0.x;
        acc.y = acc.y * scl + w * v0.y;
        acc.z = acc.z * scl + w * v1.x;
        acc.w = acc.w * scl + w * v1.y;
        m = newm;
    }

    float inv = 1.f / (s + 1e-16f);
    float4 r;
    float v;
    v = acc.x * inv; r.x = 0.5f * v * (1.f + erff(v * 0.70710678118654752f));
    v = acc.y * inv; r.y = 0.5f * v * (1.f + erff(v * 0.70710678118654752f));
    v = acc.z * inv; r.z = 0.5f * v * (1.f + erff(v * 0.70710678118654752f));
    v = acc.w * inv; r.w = 0.5f * v * (1.f + erff(v * 0.70710678118654752f));
    *(float4*)(agg + (size_t)node * 128 + c) = r;
}

// ---------------- BatchNorm (standalone; both node types per launch) ----------------
__global__ void bn_stats2(const float* __restrict__ hA, const float* __restrict__ hP,
                          float* __restrict__ stats)   // [0:256) author, [256:512) paper
{
    int c = threadIdx.x;
    const int nbA = (NA + 255) / 256;
    float s = 0.f, s2 = 0.f;
    if ((int)blockIdx.x < nbA) {
        int r0 = blockIdx.x * 256;
        int r1 = min(NA, r0 + 256);
        for (int r = r0; r < r1; r++) {
            float v = hA[(size_t)r * 128 + c];
            s += v; s2 += v * v;
        }
        atomicAdd(&stats[c], s);
        atomicAdd(&stats[128 + c], s2);
    } else {
        int r0 = (blockIdx.x - nbA) * 256;
        int r1 = min(NP, r0 + 256);
        for (int r = r0; r < r1; r++) {
            float v = hP[(size_t)r * 128 + c];
            s += v; s2 += v * v;
        }
        atomicAdd(&stats[256 + c], s);
        atomicAdd(&stats[256 + 128 + c], s2);
    }
}

__global__ void bn_apply2(const float* __restrict__ hA, const float* __restrict__ hP,
                          const float* __restrict__ stats,
                          const float* __restrict__ gamma, const float* __restrict__ beta,
                          float* __restrict__ outA, float* __restrict__ outP)
{
    int i = blockIdx.x * blockDim.x + threadIdx.x;
    const int totA = NA * 128;
    const int totP = NP * 128;
    if (i < totA) {
        int c = i & 127;
        float invN = 1.f / (float)NA;
        float mu = stats[c] * invN;
        float var = stats[128 + c] * invN - mu * mu;
        outA[i] = (hA[i] - mu) * rsqrtf(var + BN_EPS) * gamma[c] + beta[c];
    } else {
        int k = i - totA;
        if (k >= totP) return;
        int c = k & 127;
        float invN = 1.f / (float)NP;
        float mu = stats[256 + c] * invN;
        float var = stats[256 + 128 + c] * invN - mu * mu;
        outP[k] = (hP[k] - mu) * rsqrtf(var + BN_EPS) * gamma[c] + beta[c];
    }
}

// ---------------------------------------------------------------
static inline int cdiv(long long a, long long b) { return (int)((a + b - 1) / b); }

extern "C" void kernel_launch(void* const* d_in, const int* in_sizes, int n_in,
                              void* d_out, int out_size)
{
    const float* x_author = (const float*)d_in[0];
    const float* x_paper  = (const float*)d_in[1];
    const int* writes_src = (const int*)d_in[2];
    const int* writes_dst = (const int*)d_in[3];
    const int* rev_src    = (const int*)d_in[4];
    const int* rev_dst    = (const int*)d_in[5];
    const int* cites_src  = (const int*)d_in[6];
    const int* cites_dst  = (const int*)d_in[7];
    const float* linA_W   = (const float*)d_in[8];
    const float* linA_b   = (const float*)d_in[9];
    const float* linP_W   = (const float*)d_in[10];
    const float* linP_b   = (const float*)d_in[11];
    const float* kqv_W    = (const float*)d_in[12];
    const float* kqv_b    = (const float*)d_in[13];
    const float* a_k      = (const float*)d_in[14];
    const float* a_v      = (const float*)d_in[15];
    const float* p_rel    = (const float*)d_in[16];
    const float* out_W    = (const float*)d_in[17];
    const float* out_b    = (const float*)d_in[18];
    const float* skipP    = (const float*)d_in[19];
    const float* bn_gamma = (const float*)d_in[20];
    const float* bn_beta  = (const float*)d_in[21];

    float* base = nullptr;
    cudaGetSymbolAddress((void**)&base, g_scratch);

    float* XA   = base + OFF_XA;
    float* XP   = base + OFF_XP;
    float* QA   = base + OFF_QA;
    float* QP   = base + OFF_QP;
    __half* KVP = (__half*)(base + OFF_KVP);
    __half* KVA = (__half*)(base + OFF_KVA);
    float* AGGA = base + OFF_AGGA;
    float* AGGP = base + OFF_AGGP;
    float* TMPA = base + OFF_TMPA;
    float* TMPP = base + OFF_TMPP;
    float* WC   = base + OFF_WC;
    float* WCB  = base + OFF_WCB;
    float* STA  = base + OFF_STATS;
    int* ibase  = (int*)(base + OFF_INT);
    int* ROWP   = ibase + IOFF_ROWP;
    int* ROWA   = ibase + IOFF_ROWA;
    int* CURP   = ibase + IOFF_CURP;
    int* CURA   = ibase + IOFF_CURA;
    int* SRCP   = ibase + IOFF_SRCP;
    int* SRCA   = ibase + IOFF_SRCA;
    int* BS     = ibase + IOFF_BS;

    // -------- CSR build + composite weights (x-independent) --------
    const int nbP = cdiv(NP, 1024), nbA = cdiv(NA, 1024);
    cudaMemsetAsync(CURP, 0, (size_t)NP * 4, 0);
    cudaMemsetAsync(CURA, 0, (size_t)NA * 4, 0);
    hist_kernel<<<cdiv(EW, 256), 256>>>(writes_dst, CURP, EW);
    hist_kernel<<<cdiv(EC, 256), 256>>>(cites_dst, CURP, EC);
    hist_kernel<<<cdiv(ER, 256), 256>>>(rev_dst, CURA, ER);
    scan_partial<<<nbP, 256>>>(CURP, ROWP, BS, NP);
    scan_small<<<1, 256>>>(BS, nbP);
    add_off<<<cdiv(NP, 256), 256>>>(ROWP, CURP, BS, NP, nbP);
    scan_partial<<<nbA, 256>>>(CURA, ROWA, BS, NA);
    scan_small<<<1, 256>>>(BS, nbA);
    add_off<<<cdiv(NA, 256), 256>>>(ROWA, CURA, BS, NA, nbA);
    scatter_kernel<<<cdiv(EW, 256), 256>>>(writes_src, writes_dst, CURP, SRCP, EW, 0);
    scatter_kernel<<<cdiv(EC, 256), 256>>>(cites_src, cites_dst, CURP, SRCP, EC, NA);
    scatter_kernel<<<cdiv(ER, 256), 256>>>(rev_src, rev_dst, CURA, SRCA, ER, 0);
    wcomp<<<768, 256>>>(kqv_W, a_k, a_v, WC);
    bcomp<<<6, 256>>>(kqv_b, a_k, a_v, WCB);

    // -------- input projections + relu --------
    gemm_tf32<<<dim3(1, cdiv(NA, 128)), 256>>>(x_author, 128, linA_W, 128, linA_b,
                                               XA, nullptr, 128, NA, 128, 1, nullptr, nullptr);
    gemm_tf32<<<dim3(1, cdiv(NP, 128)), 256>>>(x_paper, 128, linP_W, 128, linP_b,
                                               XP, nullptr, 128, NP, 128, 1, nullptr, nullptr);

    for (int l = 0; l < 2; l++) {
        // Q projections (Q slice of kqv weights: cols [128,256))
        gemm_tf32<<<dim3(1, cdiv(NA, 128)), 256>>>(XA, 128, kqv_W + (size_t)(l * 2 + 0) * 128 * 384 + 128, 384,
                                                   kqv_b + (size_t)(l * 2 + 0) * 384 + 128,
                                                   QA, nullptr, 128, NA, 128, 0, nullptr, nullptr);
        gemm_tf32<<<dim3(1, cdiv(NP, 128)), 256>>>(XP, 128, kqv_W + (size_t)(l * 2 + 1) * 128 * 384 + 128, 384,
                                                   kqv_b + (size_t)(l * 2 + 1) * 384 + 128,
                                                   QP, nullptr, 128, NP, 128, 0, nullptr, nullptr);

        // combined K|V tables via composite weights, fp16 output
        gemm_tf32<<<dim3(2, cdiv(NA, 128)), 256>>>(XA, 128, WC + (size_t)(l * 3 + 0) * 128 * 256, 256,
                                                   WCB + (size_t)(l * 3 + 0) * 256,
                                                   nullptr, KVP, 256, NA, 128, 0, nullptr, nullptr);
        gemm_tf32<<<dim3(2, cdiv(NP, 128)), 256>>>(XP, 128, WC + (size_t)(l * 3 + 2) * 128 * 256, 256,
                                                   WCB + (size_t)(l * 3 + 2) * 256,
                                                   nullptr, KVP + (size_t)NA * 256, 256, NP, 128, 0, nullptr, nullptr);
        gemm_tf32<<<dim3(2, cdiv(NP, 128)), 256>>>(XP, 128, WC + (size_t)(l * 3 + 1) * 128 * 256, 256,
                                                   WCB + (size_t)(l * 3 + 1) * 256,
                                                   nullptr, KVA, 256, NP, 128, 0, nullptr, nullptr);

        // fused attention + softmax + aggregation + gelu (single launch, both types)
        attn_agg2<<<cdiv((long long)(NP + NA) * 32, 256), 256>>>(
            QP, KVP, ROWP, SRCP,
            p_rel + (size_t)(l * 3 + 0) * NH, p_rel + (size_t)(l * 3 + 2) * NH,
            QA, KVA, ROWA, SRCA,
            p_rel + (size_t)(l * 3 + 1) * NH,
            AGGP, AGGA);

        // output projection + fused sigmoid-skip mix (exact R8 GEMM)
        gemm_tf32<<<dim3(1, cdiv(NA, 128)), 256>>>(AGGA, 128, out_W + (size_t)(l * 2 + 0) * 128 * 128, 128,
                                                   out_b + (size_t)(l * 2 + 0) * 128,
                                                   TMPA, nullptr, 128, NA, 128, 2, XA, skipP + (l * 2 + 0));
        gemm_tf32<<<dim3(1, cdiv(NP, 128)), 256>>>(AGGP, 128, out_W + (size_t)(l * 2 + 1) * 128 * 128, 128,
                                                   out_b + (size_t)(l * 2 + 1) * 128,
                                                   TMPP, nullptr, 128, NP, 128, 2, XP, skipP + (l * 2 + 1));

        // batch norm: stats then apply, both node types per launch
        cudaMemsetAsync(STA, 0, 512 * 4, 0);
        bn_stats2<<<cdiv(NA, 256) + cdiv(NP, 256), 128>>>(TMPA, TMPP, STA);
        float* outA = (l == 1) ? (float*)d_out : XA;
        float* outP = (l == 1) ? (float*)d_out + (size_t)NA * 128 : XP;
        bn_apply2<<<cdiv((long long)(NA + NP) * 128, 256), 256>>>(TMPA, TMPP, STA,
                                                                  bn_gamma + (size_t)l * 128,
                                                                  bn_beta + (size_t)l * 128,
                                                                  outA, outP);
    }
}